// round 1
// baseline (speedup 1.0000x reference)
#include <cuda_runtime.h>
#include <math.h>

#define DIM   512
#define NH    8
#define HD    64
#define SEQ   2048
#define BATCH 2
#define MTOT  (BATCH * SEQ)   // 4096
#define KIN   (2 * DIM)       // 1024

// Scratch (device globals: no allocation allowed in kernel_launch)
__device__ float g_Q[BATCH * NH * SEQ * HD];   // 8 MB, [b,h,s,d]
__device__ float g_K[BATCH * NH * SEQ * HD];
__device__ float g_V[BATCH * NH * SEQ * HD];
__device__ float g_att[BATCH * SEQ * DIM];     // [b,s,h*64+d]

// ---------------------------------------------------------------------------
// Projection GEMM: Y[m,n] = concat(xr,xi)[m,:] @ W[:,n] + bias[n]
// written into [b,h,s,d] layout. M=4096, N=512, K=1024.
// 64x64 tile, BK=16, 256 threads, 4x4 register tile.
// ---------------------------------------------------------------------------
__global__ __launch_bounds__(256) void proj_gemm(
    const float* __restrict__ xr, const float* __restrict__ xi,
    const float* __restrict__ W,  const float* __restrict__ bias,
    float* __restrict__ out)
{
    __shared__ float As[16][64];   // A transposed: As[k][m]
    __shared__ float Bs[16][64];

    const int tid = threadIdx.x;
    const int tx = tid & 15, ty = tid >> 4;
    const int m0 = blockIdx.y * 64;
    const int n0 = blockIdx.x * 64;

    float acc[4][4] = {};

    for (int kt = 0; kt < KIN; kt += 16) {
        // A tile: 64 rows x 16 cols, one float4 per thread
        {
            int r  = tid >> 2;          // 0..63
            int c4 = (tid & 3) << 2;    // 0,4,8,12
            int gm = m0 + r;
            const float* src = (kt < DIM)
                ? (xr + (size_t)gm * DIM + kt + c4)
                : (xi + (size_t)gm * DIM + (kt - DIM) + c4);
            float4 v = *(const float4*)src;
            As[c4 + 0][r] = v.x; As[c4 + 1][r] = v.y;
            As[c4 + 2][r] = v.z; As[c4 + 3][r] = v.w;
        }
        // B tile: 16 rows x 64 cols, one float4 per thread
        {
            int r  = tid >> 4;          // 0..15
            int c4 = (tid & 15) << 2;   // 0..60
            float4 v = *(const float4*)(W + (size_t)(kt + r) * DIM + n0 + c4);
            *(float4*)&Bs[r][c4] = v;
        }
        __syncthreads();
#pragma unroll
        for (int kk = 0; kk < 16; kk++) {
            float a[4], b[4];
#pragma unroll
            for (int i = 0; i < 4; i++) a[i] = As[kk][ty * 4 + i];
#pragma unroll
            for (int j = 0; j < 4; j++) b[j] = Bs[kk][tx * 4 + j];
#pragma unroll
            for (int i = 0; i < 4; i++)
#pragma unroll
                for (int j = 0; j < 4; j++)
                    acc[i][j] = fmaf(a[i], b[j], acc[i][j]);
        }
        __syncthreads();
    }

    // epilogue: n0 is 64-aligned -> single head per block
    const int h = n0 >> 6;
    float bb[4];
#pragma unroll
    for (int j = 0; j < 4; j++) bb[j] = bias[n0 + tx * 4 + j];
#pragma unroll
    for (int i = 0; i < 4; i++) {
        int m = m0 + ty * 4 + i;
        int b = m >> 11;           // /2048
        int s = m & (SEQ - 1);
        float4 v;
        v.x = acc[i][0] + bb[0];
        v.y = acc[i][1] + bb[1];
        v.z = acc[i][2] + bb[2];
        v.w = acc[i][3] + bb[3];
        *(float4*)&out[(((size_t)(b * NH + h) * SEQ + s) * HD) + tx * 4] = v;
    }
}

// ---------------------------------------------------------------------------
// In-place sqrt(softmax(row)) over 64-wide rows. One warp per row.
// ---------------------------------------------------------------------------
__global__ __launch_bounds__(256) void softmax_sqrt(float* __restrict__ buf)
{
    int gw   = (blockIdx.x * blockDim.x + threadIdx.x) >> 5;
    int lane = threadIdx.x & 31;
    float* row = buf + (size_t)gw * HD;

    float v0 = row[lane], v1 = row[lane + 32];
    float m = fmaxf(v0, v1);
#pragma unroll
    for (int o = 16; o; o >>= 1) m = fmaxf(m, __shfl_xor_sync(0xffffffffu, m, o));
    float e0 = expf(v0 - m), e1 = expf(v1 - m);
    float ssum = e0 + e1;
#pragma unroll
    for (int o = 16; o; o >>= 1) ssum += __shfl_xor_sync(0xffffffffu, ssum, o);
    float inv = 1.0f / ssum;
    row[lane]      = sqrtf(e0 * inv);
    row[lane + 32] = sqrtf(e1 * inv);
}

// ---------------------------------------------------------------------------
// Attention: for one (b,h) and a 64-row i-tile:
//   bc = sp_i . sq_j  (d=64), w = exp(-acos(clamp(bc))^2),
//   o_i = sum_j w * V_j ; den_i = sum_j w ; out = o/den.
// Scores are in [-pi^2/4, 0] so no online max is needed.
// Dynamic smem: Ps[64][65] + Qs[64][65] (sq tile then w tile) + Vs[64][64].
// ---------------------------------------------------------------------------
__global__ __launch_bounds__(256) void attn_kernel(
    const float* __restrict__ sp, const float* __restrict__ sq,
    const float* __restrict__ V,  float* __restrict__ out)
{
    extern __shared__ float sm[];
    float* Ps = sm;                 // [64][65]
    float* Qs = sm + 64 * 65;       // [64][65]
    float* Vs = sm + 2 * 64 * 65;   // [64][64]

    const int tid = threadIdx.x;
    const int tx = tid & 15, ty = tid >> 4;
    const int bh = blockIdx.y;
    const int i0 = blockIdx.x * 64;

    const float* spb = sp + (size_t)bh * SEQ * HD;
    const float* sqb = sq + (size_t)bh * SEQ * HD;
    const float* Vb  = V  + (size_t)bh * SEQ * HD;

    // load sp tile (stays resident)
    for (int l = tid; l < 1024; l += 256) {
        int r = l >> 4, c4 = (l & 15) << 2;
        float4 v = *(const float4*)(spb + (size_t)(i0 + r) * HD + c4);
        Ps[r * 65 + c4 + 0] = v.x; Ps[r * 65 + c4 + 1] = v.y;
        Ps[r * 65 + c4 + 2] = v.z; Ps[r * 65 + c4 + 3] = v.w;
    }

    float o[4][4] = {};
    float den[4] = {};

    for (int j0 = 0; j0 < SEQ; j0 += 64) {
        __syncthreads();   // previous-iteration readers of Qs/Vs done
        for (int l = tid; l < 1024; l += 256) {
            int r = l >> 4, c4 = (l & 15) << 2;
            float4 v = *(const float4*)(sqb + (size_t)(j0 + r) * HD + c4);
            Qs[r * 65 + c4 + 0] = v.x; Qs[r * 65 + c4 + 1] = v.y;
            Qs[r * 65 + c4 + 2] = v.z; Qs[r * 65 + c4 + 3] = v.w;
            float4 vv = *(const float4*)(Vb + (size_t)(j0 + r) * HD + c4);
            *(float4*)&Vs[r * 64 + c4] = vv;
        }
        __syncthreads();

        // bc tile: thread -> (i = ty*4.., j = tx*4..)
        float bc[4][4] = {};
#pragma unroll 16
        for (int kk = 0; kk < 64; kk++) {
            float a[4], b[4];
#pragma unroll
            for (int i = 0; i < 4; i++) a[i] = Ps[(ty * 4 + i) * 65 + kk];
#pragma unroll
            for (int j = 0; j < 4; j++) b[j] = Qs[(tx * 4 + j) * 65 + kk];
#pragma unroll
            for (int i = 0; i < 4; i++)
#pragma unroll
                for (int j = 0; j < 4; j++)
                    bc[i][j] = fmaf(a[i], b[j], bc[i][j]);
        }

        // score transform
        float w[4][4];
#pragma unroll
        for (int i = 0; i < 4; i++)
#pragma unroll
            for (int j = 0; j < 4; j++) {
                float c = fminf(fmaxf(bc[i][j], -1.0f), 1.0f);
                float dd = acosf(c);
                float ww = expf(-dd * dd);
                w[i][j] = ww;
                den[i] += ww;
            }

        __syncthreads();   // all reads of Qs (sq) done before overwrite
#pragma unroll
        for (int i = 0; i < 4; i++)
#pragma unroll
            for (int j = 0; j < 4; j++)
                Qs[(ty * 4 + i) * 65 + tx * 4 + j] = w[i][j];
        __syncthreads();

        // o += w @ V : thread -> (i = ty*4.., dcol = tx*4..)
#pragma unroll 16
        for (int jj = 0; jj < 64; jj++) {
            float wv[4], vv[4];
#pragma unroll
            for (int i = 0; i < 4; i++) wv[i] = Qs[(ty * 4 + i) * 65 + jj];
#pragma unroll
            for (int j = 0; j < 4; j++) vv[j] = Vs[jj * 64 + tx * 4 + j];
#pragma unroll
            for (int i = 0; i < 4; i++)
#pragma unroll
                for (int j = 0; j < 4; j++)
                    o[i][j] = fmaf(wv[i], vv[j], o[i][j]);
        }
    }

    // reduce den across the 16 tx threads (reuse Vs as [64][16])
    __syncthreads();
#pragma unroll
    for (int i = 0; i < 4; i++) Vs[(ty * 4 + i) * 16 + tx] = den[i];
    __syncthreads();

    const int b = bh >> 3, h = bh & 7;
#pragma unroll
    for (int i = 0; i < 4; i++) {
        float s = 0.0f;
#pragma unroll
        for (int t = 0; t < 16; t++) s += Vs[(ty * 4 + i) * 16 + t];
        float inv = 1.0f / s;
        int srow = i0 + ty * 4 + i;
        float4 v;
        v.x = o[i][0] * inv; v.y = o[i][1] * inv;
        v.z = o[i][2] * inv; v.w = o[i][3] * inv;
        *(float4*)&out[((size_t)(b * SEQ + srow) * DIM) + h * HD + tx * 4] = v;
    }
}

// ---------------------------------------------------------------------------
// Output GEMM: out[m,n] = att[m,:] @ Wo[:,n] + bo[n]. M=4096, K=512, N=1024.
// ---------------------------------------------------------------------------
__global__ __launch_bounds__(256) void out_gemm(
    const float* __restrict__ A, const float* __restrict__ W,
    const float* __restrict__ bias, float* __restrict__ out)
{
    __shared__ float As[16][64];
    __shared__ float Bs[16][64];

    const int tid = threadIdx.x;
    const int tx = tid & 15, ty = tid >> 4;
    const int m0 = blockIdx.y * 64;
    const int n0 = blockIdx.x * 64;

    float acc[4][4] = {};

    for (int kt = 0; kt < DIM; kt += 16) {
        {
            int r  = tid >> 2;
            int c4 = (tid & 3) << 2;
            float4 v = *(const float4*)(A + (size_t)(m0 + r) * DIM + kt + c4);
            As[c4 + 0][r] = v.x; As[c4 + 1][r] = v.y;
            As[c4 + 2][r] = v.z; As[c4 + 3][r] = v.w;
        }
        {
            int r  = tid >> 4;
            int c4 = (tid & 15) << 2;
            float4 v = *(const float4*)(W + (size_t)(kt + r) * (2 * DIM) + n0 + c4);
            *(float4*)&Bs[r][c4] = v;
        }
        __syncthreads();
#pragma unroll
        for (int kk = 0; kk < 16; kk++) {
            float a[4], b[4];
#pragma unroll
            for (int i = 0; i < 4; i++) a[i] = As[kk][ty * 4 + i];
#pragma unroll
            for (int j = 0; j < 4; j++) b[j] = Bs[kk][tx * 4 + j];
#pragma unroll
            for (int i = 0; i < 4; i++)
#pragma unroll
                for (int j = 0; j < 4; j++)
                    acc[i][j] = fmaf(a[i], b[j], acc[i][j]);
        }
        __syncthreads();
    }

    float bb[4];
#pragma unroll
    for (int j = 0; j < 4; j++) bb[j] = bias[n0 + tx * 4 + j];
#pragma unroll
    for (int i = 0; i < 4; i++) {
        int m = m0 + ty * 4 + i;
        float4 v;
        v.x = acc[i][0] + bb[0];
        v.y = acc[i][1] + bb[1];
        v.z = acc[i][2] + bb[2];
        v.w = acc[i][3] + bb[3];
        *(float4*)&out[(size_t)m * (2 * DIM) + n0 + tx * 4] = v;
    }
}

// ---------------------------------------------------------------------------
extern "C" void kernel_launch(void* const* d_in, const int* in_sizes, int n_in,
                              void* d_out, int out_size)
{
    const float* xr = (const float*)d_in[0];
    const float* xi = (const float*)d_in[1];
    const float* Wq = (const float*)d_in[2];
    const float* bq = (const float*)d_in[3];
    const float* Wk = (const float*)d_in[4];
    const float* bk = (const float*)d_in[5];
    const float* Wv = (const float*)d_in[6];
    const float* bv = (const float*)d_in[7];
    const float* Wo = (const float*)d_in[8];
    const float* bo = (const float*)d_in[9];
    float* out = (float*)d_out;

    float *Qp, *Kp, *Vp, *Ap;
    cudaGetSymbolAddress((void**)&Qp, g_Q);
    cudaGetSymbolAddress((void**)&Kp, g_K);
    cudaGetSymbolAddress((void**)&Vp, g_V);
    cudaGetSymbolAddress((void**)&Ap, g_att);

    dim3 gp(DIM / 64, MTOT / 64);            // (8, 64)
    proj_gemm<<<gp, 256>>>(xr, xi, Wq, bq, Qp);
    proj_gemm<<<gp, 256>>>(xr, xi, Wk, bk, Kp);
    proj_gemm<<<gp, 256>>>(xr, xi, Wv, bv, Vp);

    int rows = BATCH * NH * SEQ;             // 32768
    softmax_sqrt<<<rows / 8, 256>>>(Qp);
    softmax_sqrt<<<rows / 8, 256>>>(Kp);

    int smem = (2 * 64 * 65 + 64 * 64) * (int)sizeof(float);  // 49664 B
    cudaFuncSetAttribute(attn_kernel, cudaFuncAttributeMaxDynamicSharedMemorySize, smem);
    dim3 ga(SEQ / 64, BATCH * NH);           // (32, 16)
    attn_kernel<<<ga, 256, smem>>>(Qp, Kp, Vp, Ap);

    dim3 go((2 * DIM) / 64, MTOT / 64);      // (16, 64)
    out_gemm<<<go, 256>>>(Ap, Wo, bo, out);
}

// round 3
// speedup vs baseline: 1.3140x; 1.3140x over previous
#include <cuda_runtime.h>
#include <math.h>

#define DIM   512
#define NH    8
#define HD    64
#define SEQ   2048
#define BATCH 2
#define MTOT  (BATCH * SEQ)   // 4096
#define KIN   (2 * DIM)       // 1024

// Scratch (device globals: no allocation allowed in kernel_launch)
__device__ float g_Q[BATCH * NH * SEQ * HD];   // 8 MB, [b,h,s,d]  sqrt(softmax(Q))
__device__ float g_K[BATCH * NH * SEQ * HD];   //                  sqrt(softmax(K))
__device__ float g_V[BATCH * NH * SEQ * HD];
__device__ float g_att[MTOT * DIM];            // [b,s, h*64+d]

// ---------------------------------------------------------------------------
// Projection GEMM: Y = concat(xr,xi) @ W + b.  M=4096, N=512, K=1024.
// 128x128 block tile, BK=16, 256 threads, 8x8 register tile, double-buffered.
// If DO_SM: per-head sqrt(softmax) over d=64 fused into the epilogue.
// Output layout [b,h,s,d].
// ---------------------------------------------------------------------------
template<bool DO_SM>
__global__ __launch_bounds__(256, 2) void proj_gemm(
    const float* __restrict__ xr, const float* __restrict__ xi,
    const float* __restrict__ W,  const float* __restrict__ bias,
    float* __restrict__ out)
{
    __shared__ float As[2][16][132];   // k-major, padded (132*4 = 528 B, 16B-aligned rows)
    __shared__ float Bs[2][16][128];

    const int tid = threadIdx.x;
    const int tx = tid & 15, ty = tid >> 4;
    const int m0 = blockIdx.y * 128;
    const int n0 = blockIdx.x * 128;

    const int ar  = tid >> 2;           // 0..63 (+64 for second half)
    const int ac4 = (tid & 3) << 2;     // 0,4,8,12
    const int br  = tid >> 5;           // 0..7  (+8 for second half)
    const int bc4 = (tid & 31) << 2;    // 0..124

    float4 a0, a1, b0, b1;

    // prologue: load k-tile 0
    {
        a0 = *(const float4*)(xr + (size_t)(m0 + ar)      * DIM + ac4);
        a1 = *(const float4*)(xr + (size_t)(m0 + ar + 64) * DIM + ac4);
        b0 = *(const float4*)(W + (size_t)(br)     * DIM + n0 + bc4);
        b1 = *(const float4*)(W + (size_t)(br + 8) * DIM + n0 + bc4);
        As[0][ac4+0][ar] = a0.x; As[0][ac4+1][ar] = a0.y;
        As[0][ac4+2][ar] = a0.z; As[0][ac4+3][ar] = a0.w;
        As[0][ac4+0][ar+64] = a1.x; As[0][ac4+1][ar+64] = a1.y;
        As[0][ac4+2][ar+64] = a1.z; As[0][ac4+3][ar+64] = a1.w;
        *(float4*)&Bs[0][br][bc4]     = b0;
        *(float4*)&Bs[0][br + 8][bc4] = b1;
    }
    __syncthreads();

    float acc[8][8] = {};
    const int NIT = KIN / 16;   // 64

    for (int it = 0; it < NIT; ++it) {
        const int cur = it & 1;
        if (it + 1 < NIT) {
            const int kt = (it + 1) * 16;
            const float* base = (kt < DIM) ? xr : xi;
            const int ko = (kt < DIM) ? kt : (kt - DIM);
            a0 = *(const float4*)(base + (size_t)(m0 + ar)      * DIM + ko + ac4);
            a1 = *(const float4*)(base + (size_t)(m0 + ar + 64) * DIM + ko + ac4);
            b0 = *(const float4*)(W + (size_t)(kt + br)     * DIM + n0 + bc4);
            b1 = *(const float4*)(W + (size_t)(kt + br + 8) * DIM + n0 + bc4);
        }
#pragma unroll
        for (int kk = 0; kk < 16; ++kk) {
            float a[8], b[8];
            *(float4*)&a[0] = *(const float4*)&As[cur][kk][ty * 8];
            *(float4*)&a[4] = *(const float4*)&As[cur][kk][ty * 8 + 4];
            *(float4*)&b[0] = *(const float4*)&Bs[cur][kk][tx * 8];
            *(float4*)&b[4] = *(const float4*)&Bs[cur][kk][tx * 8 + 4];
#pragma unroll
            for (int i = 0; i < 8; i++)
#pragma unroll
                for (int j = 0; j < 8; j++)
                    acc[i][j] = fmaf(a[i], b[j], acc[i][j]);
        }
        if (it + 1 < NIT) {
            const int nxt = cur ^ 1;
            As[nxt][ac4+0][ar] = a0.x; As[nxt][ac4+1][ar] = a0.y;
            As[nxt][ac4+2][ar] = a0.z; As[nxt][ac4+3][ar] = a0.w;
            As[nxt][ac4+0][ar+64] = a1.x; As[nxt][ac4+1][ar+64] = a1.y;
            As[nxt][ac4+2][ar+64] = a1.z; As[nxt][ac4+3][ar+64] = a1.w;
            *(float4*)&Bs[nxt][br][bc4]     = b0;
            *(float4*)&Bs[nxt][br + 8][bc4] = b1;
        }
        __syncthreads();
    }

    // epilogue
    float bb[8];
#pragma unroll
    for (int j = 0; j < 8; j++) bb[j] = bias[n0 + tx * 8 + j];
    const int h  = (n0 >> 6) + (tx >> 3);
    const int d0 = (tx & 7) * 8;

#pragma unroll
    for (int i = 0; i < 8; i++) {
        const int m = m0 + ty * 8 + i;
        const int b = m >> 11;
        const int s = m & (SEQ - 1);
        float v[8];
#pragma unroll
        for (int j = 0; j < 8; j++) v[j] = acc[i][j] + bb[j];
        if (DO_SM) {
            // softmax over 64 = 8 lanes (same head group) x 8 values, then sqrt
            float mx = v[0];
#pragma unroll
            for (int j = 1; j < 8; j++) mx = fmaxf(mx, v[j]);
#pragma unroll
            for (int off = 1; off < 8; off <<= 1)
                mx = fmaxf(mx, __shfl_xor_sync(0xffffffffu, mx, off));
            float sum = 0.0f;
#pragma unroll
            for (int j = 0; j < 8; j++) { v[j] = __expf(v[j] - mx); sum += v[j]; }
#pragma unroll
            for (int off = 1; off < 8; off <<= 1)
                sum += __shfl_xor_sync(0xffffffffu, sum, off);
            const float inv = 1.0f / sum;
#pragma unroll
            for (int j = 0; j < 8; j++) v[j] = sqrtf(v[j] * inv);
        }
        float* dst = out + ((size_t)(b * NH + h) * SEQ + s) * HD + d0;
        float4 v0 = { v[0], v[1], v[2], v[3] };
        float4 v1 = { v[4], v[5], v[6], v[7] };
        *(float4*)dst       = v0;
        *(float4*)(dst + 4) = v1;
    }
}

// ---------------------------------------------------------------------------
// Attention. Per block: 128 i-rows of one (b,h); sweep j in 64-tiles.
//   bc = sp_i . sq_j   (bc in [0,1] since sp,sq >= 0)
//   acos(1-u)^2 = sum_n 2^(n+1) u^n / (n^2 C(2n,n))   (degree-10, tail folded)
//   w = exp(-acos^2),  o_i = sum_j w V_j,  den_i = sum_j w,  out = o/den.
// smem: Ps[64][132] (sp, d-major), Qs[64][68] (sq, d-major),
//       Vs[64][64] (j-major), Ws[128][68] (w, i-major).
// All row strides are multiples of 4 floats -> LDS.128-safe.
// ---------------------------------------------------------------------------
__global__ __launch_bounds__(256, 2) void attn_kernel(
    const float* __restrict__ sp, const float* __restrict__ sq,
    const float* __restrict__ V,  float* __restrict__ out)
{
    extern __shared__ float sm[];
    float* Ps = sm;                        // [64][132]
    float* Qs = Ps + 64 * 132;             // [64][68]
    float* Vs = Qs + 64 * 68;              // [64][64]
    float* Ws = Vs + 64 * 64;              // [128][68]

    const int tid = threadIdx.x;
    const int tx = tid & 15, ty = tid >> 4;
    const int bh = blockIdx.y;
    const int i0 = blockIdx.x * 128;

    const float* spb = sp + (size_t)bh * SEQ * HD;
    const float* sqb = sq + (size_t)bh * SEQ * HD;
    const float* Vb  = V  + (size_t)bh * SEQ * HD;

    // resident sp tile, transposed to d-major
#pragma unroll
    for (int p = 0; p < 8; p++) {
        int l = tid + p * 256;
        int i = l >> 4, c4 = (l & 15) << 2;
        float4 v = *(const float4*)(spb + (size_t)(i0 + i) * HD + c4);
        Ps[(c4 + 0) * 132 + i] = v.x; Ps[(c4 + 1) * 132 + i] = v.y;
        Ps[(c4 + 2) * 132 + i] = v.z; Ps[(c4 + 3) * 132 + i] = v.w;
    }

    float o[8][4] = {};
    float den[8]  = {};

    for (int j0 = 0; j0 < SEQ; j0 += 64) {
        __syncthreads();   // prior readers of Qs/Vs/Ws done
#pragma unroll
        for (int p = 0; p < 4; p++) {
            int l = tid + p * 256;
            int j = l >> 4, c4 = (l & 15) << 2;
            float4 q = *(const float4*)(sqb + (size_t)(j0 + j) * HD + c4);
            Qs[(c4 + 0) * 68 + j] = q.x; Qs[(c4 + 1) * 68 + j] = q.y;
            Qs[(c4 + 2) * 68 + j] = q.z; Qs[(c4 + 3) * 68 + j] = q.w;
            float4 vv = *(const float4*)(Vb + (size_t)(j0 + j) * HD + c4);
            *(float4*)&Vs[j * 64 + c4] = vv;
        }
        __syncthreads();

        // bc = Ps^T Qs : thread tile 8 i x 4 j
        float bc[8][4] = {};
#pragma unroll 16
        for (int kk = 0; kk < 64; kk++) {
            float a[8], b[4];
            *(float4*)&a[0] = *(const float4*)&Ps[kk * 132 + ty * 8];
            *(float4*)&a[4] = *(const float4*)&Ps[kk * 132 + ty * 8 + 4];
            *(float4*)&b[0] = *(const float4*)&Qs[kk * 68 + tx * 4];
#pragma unroll
            for (int i = 0; i < 8; i++)
#pragma unroll
                for (int j = 0; j < 4; j++)
                    bc[i][j] = fmaf(a[i], b[j], bc[i][j]);
        }

        // transform + write w tile (i-major)
#pragma unroll
        for (int i = 0; i < 8; i++) {
            float4 w4;
            float* wp = &w4.x;
#pragma unroll
            for (int j = 0; j < 4; j++) {
                float u = 1.0f - bc[i][j];
                u = fminf(fmaxf(u, 0.0f), 1.0f);
                // acos(1-u)^2, degree-10
                float g = 2.0705e-4f;
                g = fmaf(g, u, 2.6002e-4f);
                g = fmaf(g, u, 6.2160e-4f);
                g = fmaf(g, u, 1.52229e-3f);
                g = fmaf(g, u, 3.84800e-3f);
                g = fmaf(g, u, 1.015873e-2f);
                g = fmaf(g, u, 2.8571429e-2f);
                g = fmaf(g, u, 8.8888889e-2f);
                g = fmaf(g, u, 0.33333333f);
                g = fmaf(g, u, 2.0f);
                g *= u;
                float ww = __expf(-g);
                wp[j] = ww;
                den[i] += ww;
            }
            *(float4*)&Ws[(ty * 8 + i) * 68 + tx * 4] = w4;
        }
        __syncthreads();

        // o += w @ V : thread tile 8 i x 4 d
#pragma unroll 16
        for (int jj = 0; jj < 64; jj++) {
            float wv[8], vv[4];
#pragma unroll
            for (int i = 0; i < 8; i++) wv[i] = Ws[(ty * 8 + i) * 68 + jj];
            *(float4*)&vv[0] = *(const float4*)&Vs[jj * 64 + tx * 4];
#pragma unroll
            for (int i = 0; i < 8; i++)
#pragma unroll
                for (int j = 0; j < 4; j++)
                    o[i][j] = fmaf(wv[i], vv[j], o[i][j]);
        }
    }

    // reduce den across the 16 tx lanes (lanes with same ty are contiguous)
#pragma unroll
    for (int i = 0; i < 8; i++) {
#pragma unroll
        for (int off = 1; off < 16; off <<= 1)
            den[i] += __shfl_xor_sync(0xffffffffu, den[i], off);
    }

    const int b = bh >> 3, h = bh & 7;
#pragma unroll
    for (int i = 0; i < 8; i++) {
        const float inv = 1.0f / den[i];
        const int srow = i0 + ty * 8 + i;
        float4 v;
        v.x = o[i][0] * inv; v.y = o[i][1] * inv;
        v.z = o[i][2] * inv; v.w = o[i][3] * inv;
        *(float4*)&out[((size_t)(b * SEQ + srow) * DIM) + h * HD + tx * 4] = v;
    }
}

// ---------------------------------------------------------------------------
// Output GEMM: out = att @ Wo + bo.  M=4096, K=512, N=1024.
// Same 128x128 / 8x8 double-buffered scheme.
// ---------------------------------------------------------------------------
__global__ __launch_bounds__(256, 2) void out_gemm(
    const float* __restrict__ A, const float* __restrict__ W,
    const float* __restrict__ bias, float* __restrict__ out)
{
    __shared__ float As[2][16][132];
    __shared__ float Bs[2][16][128];

    const int tid = threadIdx.x;
    const int tx = tid & 15, ty = tid >> 4;
    const int m0 = blockIdx.y * 128;
    const int n0 = blockIdx.x * 128;

    const int ar  = tid >> 2;
    const int ac4 = (tid & 3) << 2;
    const int br  = tid >> 5;
    const int bc4 = (tid & 31) << 2;

    float4 a0, a1, b0, b1;
    {
        a0 = *(const float4*)(A + (size_t)(m0 + ar)      * DIM + ac4);
        a1 = *(const float4*)(A + (size_t)(m0 + ar + 64) * DIM + ac4);
        b0 = *(const float4*)(W + (size_t)(br)     * KIN + n0 + bc4);
        b1 = *(const float4*)(W + (size_t)(br + 8) * KIN + n0 + bc4);
        As[0][ac4+0][ar] = a0.x; As[0][ac4+1][ar] = a0.y;
        As[0][ac4+2][ar] = a0.z; As[0][ac4+3][ar] = a0.w;
        As[0][ac4+0][ar+64] = a1.x; As[0][ac4+1][ar+64] = a1.y;
        As[0][ac4+2][ar+64] = a1.z; As[0][ac4+3][ar+64] = a1.w;
        *(float4*)&Bs[0][br][bc4]     = b0;
        *(float4*)&Bs[0][br + 8][bc4] = b1;
    }
    __syncthreads();

    float acc[8][8] = {};
    const int NIT = DIM / 16;   // 32

    for (int it = 0; it < NIT; ++it) {
        const int cur = it & 1;
        if (it + 1 < NIT) {
            const int kt = (it + 1) * 16;
            a0 = *(const float4*)(A + (size_t)(m0 + ar)      * DIM + kt + ac4);
            a1 = *(const float4*)(A + (size_t)(m0 + ar + 64) * DIM + kt + ac4);
            b0 = *(const float4*)(W + (size_t)(kt + br)     * KIN + n0 + bc4);
            b1 = *(const float4*)(W + (size_t)(kt + br + 8) * KIN + n0 + bc4);
        }
#pragma unroll
        for (int kk = 0; kk < 16; ++kk) {
            float a[8], b[8];
            *(float4*)&a[0] = *(const float4*)&As[cur][kk][ty * 8];
            *(float4*)&a[4] = *(const float4*)&As[cur][kk][ty * 8 + 4];
            *(float4*)&b[0] = *(const float4*)&Bs[cur][kk][tx * 8];
            *(float4*)&b[4] = *(const float4*)&Bs[cur][kk][tx * 8 + 4];
#pragma unroll
            for (int i = 0; i < 8; i++)
#pragma unroll
                for (int j = 0; j < 8; j++)
                    acc[i][j] = fmaf(a[i], b[j], acc[i][j]);
        }
        if (it + 1 < NIT) {
            const int nxt = cur ^ 1;
            As[nxt][ac4+0][ar] = a0.x; As[nxt][ac4+1][ar] = a0.y;
            As[nxt][ac4+2][ar] = a0.z; As[nxt][ac4+3][ar] = a0.w;
            As[nxt][ac4+0][ar+64] = a1.x; As[nxt][ac4+1][ar+64] = a1.y;
            As[nxt][ac4+2][ar+64] = a1.z; As[nxt][ac4+3][ar+64] = a1.w;
            *(float4*)&Bs[nxt][br][bc4]     = b0;
            *(float4*)&Bs[nxt][br + 8][bc4] = b1;
        }
        __syncthreads();
    }

    float bb[8];
#pragma unroll
    for (int j = 0; j < 8; j++) bb[j] = bias[n0 + tx * 8 + j];
#pragma unroll
    for (int i = 0; i < 8; i++) {
        const int m = m0 + ty * 8 + i;
        float4 v0, v1;
        v0.x = acc[i][0] + bb[0]; v0.y = acc[i][1] + bb[1];
        v0.z = acc[i][2] + bb[2]; v0.w = acc[i][3] + bb[3];
        v1.x = acc[i][4] + bb[4]; v1.y = acc[i][5] + bb[5];
        v1.z = acc[i][6] + bb[6]; v1.w = acc[i][7] + bb[7];
        float* dst = out + (size_t)m * KIN + n0 + tx * 8;
        *(float4*)dst       = v0;
        *(float4*)(dst + 4) = v1;
    }
}

// ---------------------------------------------------------------------------
extern "C" void kernel_launch(void* const* d_in, const int* in_sizes, int n_in,
                              void* d_out, int out_size)
{
    const float* xr = (const float*)d_in[0];
    const float* xi = (const float*)d_in[1];
    const float* Wq = (const float*)d_in[2];
    const float* bq = (const float*)d_in[3];
    const float* Wk = (const float*)d_in[4];
    const float* bk = (const float*)d_in[5];
    const float* Wv = (const float*)d_in[6];
    const float* bv = (const float*)d_in[7];
    const float* Wo = (const float*)d_in[8];
    const float* bo = (const float*)d_in[9];
    float* out = (float*)d_out;

    float *Qp, *Kp, *Vp, *Ap;
    cudaGetSymbolAddress((void**)&Qp, g_Q);
    cudaGetSymbolAddress((void**)&Kp, g_K);
    cudaGetSymbolAddress((void**)&Vp, g_V);
    cudaGetSymbolAddress((void**)&Ap, g_att);

    dim3 gp(DIM / 128, MTOT / 128);          // (4, 32)
    proj_gemm<true ><<<gp, 256>>>(xr, xi, Wq, bq, Qp);
    proj_gemm<true ><<<gp, 256>>>(xr, xi, Wk, bk, Kp);
    proj_gemm<false><<<gp, 256>>>(xr, xi, Wv, bv, Vp);

    const int asmem = (64 * 132 + 64 * 68 + 64 * 64 + 128 * 68) * (int)sizeof(float); // 102400
    cudaFuncSetAttribute(attn_kernel, cudaFuncAttributeMaxDynamicSharedMemorySize, asmem);
    dim3 ga(SEQ / 128, BATCH * NH);          // (16, 16)
    attn_kernel<<<ga, 256, asmem>>>(Qp, Kp, Vp, Ap);

    dim3 go(KIN / 128, MTOT / 128);          // (8, 32)
    out_gemm<<<go, 256>>>(Ap, Wo, bo, out);
}